// round 9
// baseline (speedup 1.0000x reference)
#include <cuda_runtime.h>
#include <cuda_bf16.h>

#define D 64
#define D4 (D / 4)          // 16 float4 per row
#define NODES_MAX 100000
#define EDGES_MAX 1600000
#define GR 64               // gemm rows per block (smem: 16KB K + 16KB x = 32KB)
#define NB_MAX 512          // max scan blocks (supports up to 131072 nodes)

// Scratch (static device globals: allocation-free, allowed by harness rules)
__device__ float  g_deg[NODES_MAX];
__device__ float  g_dis[NODES_MAX];
__device__ int    g_cnt[NODES_MAX];       // edges per row
__device__ int    g_rowstart[NODES_MAX];  // CSR offsets (exclusive scan of cnt)
__device__ int    g_cursor[NODES_MAX];    // scatter cursors
__device__ int    g_bsum[NB_MAX];
__device__ int    g_boff[NB_MAX];
__device__ float2 g_ecw[EDGES_MAX];       // CSR payload: (col bits, wn)
__device__ float4 g_h[NODES_MAX * D4];    // h = x@K (+ id contribution)

__device__ __forceinline__ void fma4(float4& a, float s, const float4& k) {
    a.x += s * k.x; a.y += s * k.y; a.z += s * k.z; a.w += s * k.w;
}

// ---------------------------------------------------------------------------
// 1) init: deg = 1 (self loop), cnt = 0
__global__ void k_deg_init(int n_nodes) {
    int i = blockIdx.x * blockDim.x + threadIdx.x;
    if (i < n_nodes) { g_deg[i] = 1.0f; g_cnt[i] = 0; }
}

// 2) deg accumulate + per-row edge histogram
__global__ void __launch_bounds__(256) k_deg_acc(const int* __restrict__ row,
                          const float* __restrict__ w, int n_edges) {
    int e = blockIdx.x * blockDim.x + threadIdx.x;
    if (e < n_edges) {
        int r = row[e];
        atomicAdd(&g_deg[r], w[e]);
        atomicAdd(&g_cnt[r], 1);
    }
}

// 3) fused: dis = rsqrt(deg)  AND  scan pass 1 (per-block sums of cnt)
__global__ void k_dis_scan1(int n_nodes) {
    __shared__ int sh[256];
    int t = threadIdx.x;
    int i = blockIdx.x * 256 + t;
    int c = 0;
    if (i < n_nodes) {
        g_dis[i] = rsqrtf(g_deg[i]);
        c = g_cnt[i];
    }
    sh[t] = c;
    __syncthreads();
    for (int o = 128; o > 0; o >>= 1) {
        if (t < o) sh[t] += sh[t + o];
        __syncthreads();
    }
    if (t == 0) g_bsum[blockIdx.x] = sh[0];
}

// 3b) scan pass 2: exclusive scan of block sums (single block, 512 thr)
__global__ void k_scan2(int nb) {
    __shared__ int sh[NB_MAX];
    int t = threadIdx.x;
    int v = (t < nb) ? g_bsum[t] : 0;
    sh[t] = v;
    __syncthreads();
    for (int o = 1; o < NB_MAX; o <<= 1) {
        int a = (t >= o) ? sh[t - o] : 0;
        __syncthreads();
        sh[t] += a;
        __syncthreads();
    }
    g_boff[t] = sh[t] - v;   // exclusive
}

// 3c) scan pass 3: per-block exclusive scan + block offset -> rowstart, cursor
__global__ void k_scan3(int n_nodes) {
    __shared__ int sh[256];
    int t = threadIdx.x;
    int i = blockIdx.x * 256 + t;
    int v = (i < n_nodes) ? g_cnt[i] : 0;
    sh[t] = v;
    __syncthreads();
    for (int o = 1; o < 256; o <<= 1) {
        int a = (t >= o) ? sh[t - o] : 0;
        __syncthreads();
        sh[t] += a;
        __syncthreads();
    }
    int excl = sh[t] - v + g_boff[blockIdx.x];
    if (i < n_nodes) { g_rowstart[i] = excl; g_cursor[i] = excl; }
}

// 4) scatter edges into CSR slots with precomputed normalized weight
__global__ void __launch_bounds__(256) k_scatter(const int* __restrict__ row,
                      const int* __restrict__ col,
                      const float* __restrict__ w, int n_edges) {
    int e = blockIdx.x * blockDim.x + threadIdx.x;
    if (e < n_edges) {
        int r = __ldg(&row[e]);
        int c = __ldg(&col[e]);
        float wn = g_dis[r] * __ldg(&w[e]) * g_dis[c];
        int pos = atomicAdd(&g_cursor[r], 1);
        g_ecw[pos] = make_float2(__int_as_float(c), wn);
    }
}

// 5) h = x @ K.  Block: 256 thr -> 64x64 tile, 32KB static smem.
__global__ void __launch_bounds__(256) k_gemm(const float4* __restrict__ x4,
                                              const float4* __restrict__ K4,
                                              int n_nodes) {
    __shared__ float4 sK4[D * 16];
    __shared__ float4 sX4[GR * 16];
    int tid  = threadIdx.x;
    int row0 = blockIdx.x * GR;

    for (int i = tid; i < D * 16; i += 256) sK4[i] = K4[i];
    {
        int i = tid;
#pragma unroll
        for (int it = 0; it < 4; it++, i += 256) {
            int gr = row0 + (i >> 4);
            sX4[i] = (gr < n_nodes) ? x4[gr * 16 + (i & 15)]
                                    : make_float4(0.f, 0.f, 0.f, 0.f);
        }
    }
    __syncthreads();

    int rg = tid >> 4;
    int cg = tid & 15;

    float4 acc[4];
#pragma unroll
    for (int i = 0; i < 4; i++) acc[i] = make_float4(0.f, 0.f, 0.f, 0.f);

#pragma unroll
    for (int kc = 0; kc < 16; kc++) {
        float4 xv[4];
#pragma unroll
        for (int i = 0; i < 4; i++) xv[i] = sX4[(rg * 4 + i) * 16 + kc];
#pragma unroll
        for (int kk = 0; kk < 4; kk++) {
            float4 kv = sK4[(kc * 4 + kk) * 16 + cg];
#pragma unroll
            for (int i = 0; i < 4; i++) {
                float s = reinterpret_cast<const float*>(&xv[i])[kk];
                fma4(acc[i], s, kv);
            }
        }
    }

#pragma unroll
    for (int i = 0; i < 4; i++) {
        int gr = row0 + rg * 4 + i;
        if (gr < n_nodes) g_h[gr * 16 + cg] = acc[i];
    }
}

// 6) h[id_index[t]] += x[id_index[t]] @ K_id  (atomic: id_index may repeat)
__global__ void k_gemm_id(const float* __restrict__ x,
                          const float* __restrict__ Kid,
                          const int* __restrict__ id_index, int n_id) {
    __shared__ float sK[D][D];
    int tid = threadIdx.x;
    for (int i = tid; i < D * D; i += 256) sK[i >> 6][i & 63] = Kid[i];
    __syncthreads();
    int r = tid >> 6;
    int j = tid & 63;
    int t = blockIdx.x * 4 + r;
    if (t < n_id) {
        int node = __ldg(&id_index[t]);
        const float* xr = x + node * D;
        float acc = 0.0f;
#pragma unroll
        for (int k = 0; k < D; k++) acc += __ldg(&xr[k]) * sK[k][j];
        atomicAdd(&reinterpret_cast<float*>(g_h)[node * D + j], acc);
    }
}

// 7) CSR SpMM: one warp per row; halfwarves own even/odd edges; 4-way unroll
//    gives each halfwarp 4 independent gathers in flight (MLP 8/warp).
//    out[r] = bias + dis[r]^2 * h[r] + sum_e wn[e] * h[col[e]]   (no atomics)
__global__ void __launch_bounds__(256) k_spmm_csr(const float4* __restrict__ bias4,
                       float4* __restrict__ out, int n_nodes) {
    int r    = (blockIdx.x * blockDim.x + threadIdx.x) >> 5;
    int lane = threadIdx.x & 31;
    if (r >= n_nodes) return;
    int base = g_rowstart[r];
    int deg  = g_cnt[r];
    int half = lane >> 4;     // 0: even edges, 1: odd edges
    int l    = lane & 15;     // float4 column

    float4 a0 = make_float4(0.f, 0.f, 0.f, 0.f);
    float4 a1 = make_float4(0.f, 0.f, 0.f, 0.f);

    int i = half;
    // 4 edges per halfwarp per iteration: i, i+2, i+4, i+6
    for (; i + 6 < deg; i += 8) {
        float2 e0 = __ldg(&g_ecw[base + i]);
        float2 e1 = __ldg(&g_ecw[base + i + 2]);
        float2 e2 = __ldg(&g_ecw[base + i + 4]);
        float2 e3 = __ldg(&g_ecw[base + i + 6]);
        float4 h0 = g_h[__float_as_int(e0.x) * 16 + l];
        float4 h1 = g_h[__float_as_int(e1.x) * 16 + l];
        float4 h2 = g_h[__float_as_int(e2.x) * 16 + l];
        float4 h3 = g_h[__float_as_int(e3.x) * 16 + l];
        fma4(a0, e0.y, h0);
        fma4(a1, e1.y, h1);
        fma4(a0, e2.y, h2);
        fma4(a1, e3.y, h3);
    }
    for (; i < deg; i += 2) {
        float2 e = __ldg(&g_ecw[base + i]);
        fma4(a0, e.y, g_h[__float_as_int(e.x) * 16 + l]);
    }
    a0.x += a1.x; a0.y += a1.y; a0.z += a1.z; a0.w += a1.w;

    // combine odd-half into even-half
    a0.x += __shfl_down_sync(0xffffffffu, a0.x, 16);
    a0.y += __shfl_down_sync(0xffffffffu, a0.y, 16);
    a0.z += __shfl_down_sync(0xffffffffu, a0.z, 16);
    a0.w += __shfl_down_sync(0xffffffffu, a0.w, 16);

    if (half == 0) {
        float s = g_dis[r];
        s = s * s;
        float4 hv = g_h[r * 16 + l];
        float4 b  = __ldg(&bias4[l]);
        out[r * 16 + l] = make_float4(b.x + s * hv.x + a0.x,
                                      b.y + s * hv.y + a0.y,
                                      b.z + s * hv.z + a0.z,
                                      b.w + s * hv.w + a0.w);
    }
}

extern "C" void kernel_launch(void* const* d_in, const int* in_sizes, int n_in,
                              void* d_out, int out_size) {
    const float* x        = (const float*)d_in[0];
    const int*   ei       = (const int*)d_in[1];
    const int*   id_index = (const int*)d_in[2];
    const float* ew       = (const float*)d_in[3];
    const float* K        = (const float*)d_in[4];
    const float* Kid      = (const float*)d_in[5];
    const float* bias     = (const float*)d_in[6];
    float*       out      = (float*)d_out;

    int n_nodes = in_sizes[0] / D;
    int n_edges = in_sizes[1] / 2;
    int n_id    = in_sizes[2];
    int nb      = (n_nodes + 255) / 256;

    const int* row  = ei;
    const int* colp = ei + n_edges;

    k_deg_init<<<nb, 256>>>(n_nodes);
    k_deg_acc<<<(n_edges + 255) / 256, 256>>>(row, ew, n_edges);
    k_dis_scan1<<<nb, 256>>>(n_nodes);
    k_scan2<<<1, NB_MAX>>>(nb);
    k_scan3<<<nb, 256>>>(n_nodes);
    k_scatter<<<(n_edges + 255) / 256, 256>>>(row, colp, ew, n_edges);
    k_gemm<<<(n_nodes + GR - 1) / GR, 256>>>((const float4*)x,
                                             (const float4*)K, n_nodes);
    k_gemm_id<<<(n_id + 3) / 4, 256>>>(x, Kid, id_index, n_id);
    k_spmm_csr<<<(n_nodes * 32 + 255) / 256, 256>>>((const float4*)bias,
                                                    (float4*)out, n_nodes);
}

// round 10
// speedup vs baseline: 1.0553x; 1.0553x over previous
#include <cuda_runtime.h>
#include <cuda_fp16.h>

#define D 64
#define NODES_MAX 100000
#define EDGES_MAX 1600000
#define GR 64               // gemm rows per block (smem: 16KB K + 16KB x = 32KB)
#define NB_MAX 512

// Scratch (static device globals: allocation-free, allowed by harness rules)
__device__ float  g_deg[NODES_MAX];
__device__ float  g_dis[NODES_MAX];
__device__ int    g_cnt[NODES_MAX];       // edges per row
__device__ int    g_rowstart[NODES_MAX];  // CSR offsets
__device__ int    g_cursor[NODES_MAX];    // scatter cursors
__device__ int    g_bsum[NB_MAX];         // per-block cnt sums
__device__ float2 g_ecw[EDGES_MAX];       // CSR payload: (col bits, wn)
__device__ float4 g_h[NODES_MAX * 16];    // fp32 h (master, 25.6 MB)
__device__ uint2  g_h16[NODES_MAX * 16];  // fp16 h mirror (4 halves/entry, 12.8 MB)

__device__ __forceinline__ void fma4(float4& a, float s, const float4& k) {
    a.x += s * k.x; a.y += s * k.y; a.z += s * k.z; a.w += s * k.w;
}

__device__ __forceinline__ uint2 f4_to_h16(float4 a) {
    __half2 lo = __floats2half2_rn(a.x, a.y);
    __half2 hi = __floats2half2_rn(a.z, a.w);
    uint2 u;
    u.x = *reinterpret_cast<const unsigned*>(&lo);
    u.y = *reinterpret_cast<const unsigned*>(&hi);
    return u;
}

__device__ __forceinline__ float4 h16_to_f4(uint2 u) {
    __half2 lo = *reinterpret_cast<const __half2*>(&u.x);
    __half2 hi = *reinterpret_cast<const __half2*>(&u.y);
    float2 f0 = __half22float2(lo);
    float2 f1 = __half22float2(hi);
    return make_float4(f0.x, f0.y, f1.x, f1.y);
}

// ---------------------------------------------------------------------------
// 1) init: deg = 1 (self loop), cnt = 0
__global__ void k_deg_init(int n_nodes) {
    int i = blockIdx.x * blockDim.x + threadIdx.x;
    if (i < n_nodes) { g_deg[i] = 1.0f; g_cnt[i] = 0; }
}

// 2) deg accumulate + per-row edge histogram
__global__ void __launch_bounds__(256) k_deg_acc(const int* __restrict__ row,
                          const float* __restrict__ w, int n_edges) {
    int e = blockIdx.x * blockDim.x + threadIdx.x;
    if (e < n_edges) {
        int r = row[e];
        atomicAdd(&g_deg[r], w[e]);
        atomicAdd(&g_cnt[r], 1);
    }
}

// 3) fused: dis = rsqrt(deg) AND scan pass 1 (per-block sums of cnt)
__global__ void k_dis_scan1(int n_nodes) {
    __shared__ int sh[256];
    int t = threadIdx.x;
    int i = blockIdx.x * 256 + t;
    int c = 0;
    if (i < n_nodes) {
        g_dis[i] = rsqrtf(g_deg[i]);
        c = g_cnt[i];
    }
    sh[t] = c;
    __syncthreads();
    for (int o = 128; o > 0; o >>= 1) {
        if (t < o) sh[t] += sh[t + o];
        __syncthreads();
    }
    if (t == 0) g_bsum[blockIdx.x] = sh[0];
}

// 4) scan pass 2 (fused): each block sums bsum[j<bid] inline, then does its
//    local exclusive scan -> rowstart, cursor.  (replaces old scan2+scan3)
__global__ void k_scan3(int n_nodes, int nb) {
    __shared__ int sh[256];
    __shared__ int s_boff;
    int t = threadIdx.x;

    // block offset = sum of g_bsum[j] for j < blockIdx.x
    int partial = 0;
    for (int j = t; j < blockIdx.x; j += 256) partial += g_bsum[j];
    sh[t] = partial;
    __syncthreads();
    for (int o = 128; o > 0; o >>= 1) {
        if (t < o) sh[t] += sh[t + o];
        __syncthreads();
    }
    if (t == 0) s_boff = sh[0];
    __syncthreads();

    // local inclusive scan of cnt
    int i = blockIdx.x * 256 + t;
    int v = (i < n_nodes) ? g_cnt[i] : 0;
    sh[t] = v;
    __syncthreads();
    for (int o = 1; o < 256; o <<= 1) {
        int a = (t >= o) ? sh[t - o] : 0;
        __syncthreads();
        sh[t] += a;
        __syncthreads();
    }
    int excl = sh[t] - v + s_boff;
    if (i < n_nodes) { g_rowstart[i] = excl; g_cursor[i] = excl; }
}

// 5) scatter edges into CSR slots with precomputed normalized weight
__global__ void __launch_bounds__(256) k_scatter(const int* __restrict__ row,
                      const int* __restrict__ col,
                      const float* __restrict__ w, int n_edges) {
    int e = blockIdx.x * blockDim.x + threadIdx.x;
    if (e < n_edges) {
        int r = __ldg(&row[e]);
        int c = __ldg(&col[e]);
        float wn = g_dis[r] * __ldg(&w[e]) * g_dis[c];
        int pos = atomicAdd(&g_cursor[r], 1);
        g_ecw[pos] = make_float2(__int_as_float(c), wn);
    }
}

// 6) h = x @ K.  256 thr -> 64x64 tile; writes fp32 master + fp16 mirror.
__global__ void __launch_bounds__(256) k_gemm(const float4* __restrict__ x4,
                                              const float4* __restrict__ K4,
                                              int n_nodes) {
    __shared__ float4 sK4[D * 16];
    __shared__ float4 sX4[GR * 16];
    int tid  = threadIdx.x;
    int row0 = blockIdx.x * GR;

    for (int i = tid; i < D * 16; i += 256) sK4[i] = K4[i];
    {
        int i = tid;
#pragma unroll
        for (int it = 0; it < 4; it++, i += 256) {
            int gr = row0 + (i >> 4);
            sX4[i] = (gr < n_nodes) ? x4[gr * 16 + (i & 15)]
                                    : make_float4(0.f, 0.f, 0.f, 0.f);
        }
    }
    __syncthreads();

    int rg = tid >> 4;
    int cg = tid & 15;

    float4 acc[4];
#pragma unroll
    for (int i = 0; i < 4; i++) acc[i] = make_float4(0.f, 0.f, 0.f, 0.f);

#pragma unroll
    for (int kc = 0; kc < 16; kc++) {
        float4 xv[4];
#pragma unroll
        for (int i = 0; i < 4; i++) xv[i] = sX4[(rg * 4 + i) * 16 + kc];
#pragma unroll
        for (int kk = 0; kk < 4; kk++) {
            float4 kv = sK4[(kc * 4 + kk) * 16 + cg];
#pragma unroll
            for (int i = 0; i < 4; i++) {
                float s = reinterpret_cast<const float*>(&xv[i])[kk];
                fma4(acc[i], s, kv);
            }
        }
    }

#pragma unroll
    for (int i = 0; i < 4; i++) {
        int gr = row0 + rg * 4 + i;
        if (gr < n_nodes) {
            g_h[gr * 16 + cg]   = acc[i];
            g_h16[gr * 16 + cg] = f4_to_h16(acc[i]);
        }
    }
}

// 7) h[id_index[t]] += x[id_index[t]] @ K_id  (fp32 atomics on master)
__global__ void k_gemm_id(const float* __restrict__ x,
                          const float* __restrict__ Kid,
                          const int* __restrict__ id_index, int n_id) {
    __shared__ float sK[D][D];
    int tid = threadIdx.x;
    for (int i = tid; i < D * D; i += 256) sK[i >> 6][i & 63] = Kid[i];
    __syncthreads();
    int r = tid >> 6;
    int j = tid & 63;
    int t = blockIdx.x * 4 + r;
    if (t < n_id) {
        int node = __ldg(&id_index[t]);
        const float* xr = x + node * D;
        float acc = 0.0f;
#pragma unroll
        for (int k = 0; k < D; k++) acc += __ldg(&xr[k]) * sK[k][j];
        atomicAdd(&reinterpret_cast<float*>(g_h)[node * D + j], acc);
    }
}

// 8) re-sync fp16 mirror for the id-touched rows (duplicates: idempotent)
__global__ void k_h16fix(const int* __restrict__ id_index, int n_id) {
    int t = blockIdx.x * blockDim.x + threadIdx.x;
    int i = t >> 4, l = t & 15;
    if (i < n_id) {
        int r = __ldg(&id_index[i]);
        g_h16[r * 16 + l] = f4_to_h16(g_h[r * 16 + l]);
    }
}

// 9) CSR SpMM over fp16 h: one warp per row; halfwarves own even/odd edges.
//    out[r] = bias + dis[r]^2 * h[r] + sum_e wn[e] * h[col[e]]  (no atomics)
__global__ void __launch_bounds__(256) k_spmm_csr(const float4* __restrict__ bias4,
                       float4* __restrict__ out, int n_nodes) {
    int r    = (blockIdx.x * blockDim.x + threadIdx.x) >> 5;
    int lane = threadIdx.x & 31;
    if (r >= n_nodes) return;
    int base = g_rowstart[r];
    int deg  = g_cnt[r];
    int half = lane >> 4;     // 0: even edges, 1: odd edges
    int l    = lane & 15;     // column group (4 cols)

    float4 acc = make_float4(0.f, 0.f, 0.f, 0.f);
    for (int i = half; i < deg; i += 2) {
        float2 e = __ldg(&g_ecw[base + i]);
        float4 hv = h16_to_f4(__ldg(&g_h16[__float_as_int(e.x) * 16 + l]));
        fma4(acc, e.y, hv);
    }

    // combine odd-half into even-half
    acc.x += __shfl_down_sync(0xffffffffu, acc.x, 16);
    acc.y += __shfl_down_sync(0xffffffffu, acc.y, 16);
    acc.z += __shfl_down_sync(0xffffffffu, acc.z, 16);
    acc.w += __shfl_down_sync(0xffffffffu, acc.w, 16);

    if (half == 0) {
        float s = g_dis[r];
        s = s * s;
        float4 hv = h16_to_f4(__ldg(&g_h16[r * 16 + l]));
        float4 b  = __ldg(&bias4[l]);
        out[r * 16 + l] = make_float4(b.x + s * hv.x + acc.x,
                                      b.y + s * hv.y + acc.y,
                                      b.z + s * hv.z + acc.z,
                                      b.w + s * hv.w + acc.w);
    }
}

extern "C" void kernel_launch(void* const* d_in, const int* in_sizes, int n_in,
                              void* d_out, int out_size) {
    const float* x        = (const float*)d_in[0];
    const int*   ei       = (const int*)d_in[1];
    const int*   id_index = (const int*)d_in[2];
    const float* ew       = (const float*)d_in[3];
    const float* K        = (const float*)d_in[4];
    const float* Kid      = (const float*)d_in[5];
    const float* bias     = (const float*)d_in[6];
    float*       out      = (float*)d_out;

    int n_nodes = in_sizes[0] / D;
    int n_edges = in_sizes[1] / 2;
    int n_id    = in_sizes[2];
    int nb      = (n_nodes + 255) / 256;

    const int* row  = ei;
    const int* colp = ei + n_edges;

    k_deg_init<<<nb, 256>>>(n_nodes);
    k_deg_acc<<<(n_edges + 255) / 256, 256>>>(row, ew, n_edges);
    k_dis_scan1<<<nb, 256>>>(n_nodes);
    k_scan3<<<nb, 256>>>(n_nodes, nb);
    k_scatter<<<(n_edges + 255) / 256, 256>>>(row, colp, ew, n_edges);
    k_gemm<<<(n_nodes + GR - 1) / GR, 256>>>((const float4*)x,
                                             (const float4*)K, n_nodes);
    k_gemm_id<<<(n_id + 3) / 4, 256>>>(x, Kid, id_index, n_id);
    k_h16fix<<<(n_id * 16 + 255) / 256, 256>>>(id_index, n_id);
    k_spmm_csr<<<(n_nodes * 32 + 255) / 256, 256>>>((const float4*)bias,
                                                    (float4*)out, n_nodes);
}